// round 11
// baseline (speedup 1.0000x reference)
#include <cuda_runtime.h>
#include <cuda_bf16.h>
#include <cstdint>

// ---------------------------------------------------------------------------
// DIN forward, round 11 (round-10 resubmit; previous bench was an infra
// container failure, kernel never ran).
//   k0 (512 CTAs x 16 rows): weight folding (grid-stride) + batched cand
//       projections (qrel/Wv table, cand embedding table).
//   din_mma (8192 CTAs): stage ceil8(len) rows -> bf16 m16n8k16 score GEMM,
//       2mt x 4nq warp tiling (each B fragment feeds 2 MMAs) -> softmax ->
//       len-bounded fp32 pooling -> pooled vectors.
//   k2 (1024 CTAs x 8 rows): E-projection + BN-folded MLP + sigmoid.
// ---------------------------------------------------------------------------

#define EPSBN 1e-5f

// ---- device scratch ----
__device__ uint4  d_Afrag4[4 * 8 * 32];   // [mt][k][lane] bf16x2 A-fragments
__device__ float  d_W1f[192 * 128];       // BN-folded MLP weights [in][out]
__device__ float  d_b1f[128];
__device__ float  d_W2f[128 * 64];
__device__ float  d_b2f[64];
__device__ float  d_W3f[64 * 32];
__device__ float  d_b3f[32];
__device__ float2 d_Qv[8192 * 64];        // (qrel, Wv) per (b, a)
__device__ float  d_CandE[8192 * 64];     // cand embedding (with bi)
__device__ float  d_Pool[8192 * 256];     // [spa(128) | spv(128)] per b

// ---- packed f32x2 helpers ----
__device__ __forceinline__ unsigned long long ffma2(unsigned long long a,
                                                    unsigned long long b,
                                                    unsigned long long c) {
    unsigned long long d;
    asm("fma.rn.f32x2 %0, %1, %2, %3;" : "=l"(d) : "l"(a), "l"(b), "l"(c));
    return d;
}
__device__ __forceinline__ unsigned long long fadd2(unsigned long long a,
                                                    unsigned long long b) {
    unsigned long long d;
    asm("add.rn.f32x2 %0, %1, %2;" : "=l"(d) : "l"(a), "l"(b));
    return d;
}
__device__ __forceinline__ unsigned long long pack2(float lo, float hi) {
    unsigned long long r;
    asm("mov.b64 %0, {%1, %2};" : "=l"(r) : "f"(lo), "f"(hi));
    return r;
}

// bf16 mma: D += A*B (A row-major m16k16, B col-major k16n8, fp32 acc)
__device__ __forceinline__ void mma_bf16(float c[4], uint32_t a0, uint32_t a1,
                                         uint32_t a2, uint32_t a3,
                                         uint32_t b0, uint32_t b1) {
    asm volatile(
        "mma.sync.aligned.m16n8k16.row.col.f32.bf16.bf16.f32 "
        "{%0,%1,%2,%3}, {%4,%5,%6,%7}, {%8,%9}, {%0,%1,%2,%3};"
        : "+f"(c[0]), "+f"(c[1]), "+f"(c[2]), "+f"(c[3])
        : "r"(a0), "r"(a1), "r"(a2), "r"(a3), "r"(b0), "r"(b1));
}

// ---------------------------------------------------------------------------
// k0: weight folds (grid-stride) + per-CTA batched cand projections.
// 512 CTAs x 256 threads; 16 batch rows per CTA.
// ---------------------------------------------------------------------------
__global__ __launch_bounds__(256) void k0_kernel(
    const float* __restrict__ cand,
    const float* __restrict__ Wi, const float* __restrict__ bi,
    const float* __restrict__ Wq, const float* __restrict__ Wk,
    const float* __restrict__ Wv,
    const float* __restrict__ W1, const float* __restrict__ b1,
    const float* __restrict__ g1, const float* __restrict__ be1,
    const float* __restrict__ m1, const float* __restrict__ v1,
    const float* __restrict__ W2, const float* __restrict__ b2,
    const float* __restrict__ g2, const float* __restrict__ be2,
    const float* __restrict__ m2, const float* __restrict__ v2,
    const float* __restrict__ W3, const float* __restrict__ b3,
    const float* __restrict__ g3, const float* __restrict__ be3,
    const float* __restrict__ m3, const float* __restrict__ v3)
{
    __shared__ float sc[16 * 128];   // cand rows; later overlaid by cand_emb
    __shared__ float sbk[64];

    const int tid = threadIdx.x;
    const int bid = blockIdx.x;
    const int t0 = bid * 256 + tid;
    const int stride = gridDim.x * 256;

    // ---- grid-stride weight folding ----
    for (int idx = t0; idx < 1024; idx += stride) {
        const int lane = idx & 31;
        const int k8   = (idx >> 5) & 7;
        const int mt   = idx >> 8;
        uint32_t comp[4];
        #pragma unroll
        for (int j = 0; j < 4; j++) {
            const int a  = mt * 16 + (lane >> 2) + ((j & 1) << 3);
            const int f0 = k8 * 16 + 2 * (lane & 3) + ((j >> 1) << 3);
            float s0 = 0.f, s1 = 0.f;
            for (int e = 0; e < 64; e++) {
                const float wka = Wk[e * 64 + a];
                s0 = fmaf(Wi[f0 * 64 + e],       wka, s0);
                s1 = fmaf(Wi[(f0 + 1) * 64 + e], wka, s1);
            }
            __nv_bfloat162 pr = __floats2bfloat162_rn(s0, s1);
            comp[j] = *(uint32_t*)&pr;
        }
        d_Afrag4[idx] = make_uint4(comp[0], comp[1], comp[2], comp[3]);
    }
    for (int idx = t0; idx < 192 * 128; idx += stride) {
        const int h = idx & 127;
        d_W1f[idx] = W1[idx] * (g1[h] * rsqrtf(v1[h] + EPSBN));
    }
    for (int h = t0; h < 128; h += stride) {
        const float scl = g1[h] * rsqrtf(v1[h] + EPSBN);
        d_b1f[h] = (b1[h] - m1[h]) * scl + be1[h];
    }
    for (int idx = t0; idx < 128 * 64; idx += stride) {
        const int h = idx & 63;
        d_W2f[idx] = W2[idx] * (g2[h] * rsqrtf(v2[h] + EPSBN));
    }
    for (int h = t0; h < 64; h += stride) {
        const float scl = g2[h] * rsqrtf(v2[h] + EPSBN);
        d_b2f[h] = (b2[h] - m2[h]) * scl + be2[h];
    }
    for (int idx = t0; idx < 64 * 32; idx += stride) {
        const int h = idx & 31;
        d_W3f[idx] = W3[idx] * (g3[h] * rsqrtf(v3[h] + EPSBN));
    }
    for (int h = t0; h < 32; h += stride) {
        const float scl = g3[h] * rsqrtf(v3[h] + EPSBN);
        d_b3f[h] = (b3[h] - m3[h]) * scl + be3[h];
    }

    // ---- per-CTA: 16 candidate rows ----
    const long rbase = (long)bid * 16;
    for (int i = tid; i < 16 * 32; i += 256)
        ((float4*)sc)[i] = ((const float4*)(cand + rbase * 128))[i];
    if (tid < 64) {   // bk[a] = bi @ Wk[:,a]
        float s = 0.f;
        for (int e = 0; e < 64; e++)
            s = fmaf(bi[e], Wk[e * 64 + tid], s);
        sbk[tid] = s;
    }
    __syncthreads();

    // cand_emb: thread (e = tid&63, rg = tid>>6) handles 4 rows
    const int e  = tid & 63;
    const int rg = tid >> 6;
    float emb[4];
    {
        #pragma unroll
        for (int r = 0; r < 4; r++) emb[r] = bi[e];
        for (int f = 0; f < 128; f++) {
            const float wv = Wi[f * 64 + e];
            #pragma unroll
            for (int r = 0; r < 4; r++)
                emb[r] = fmaf(sc[(rg * 4 + r) * 128 + f], wv, emb[r]);
        }
    }
    __syncthreads();    // sc reads done; overlay emb
    #pragma unroll
    for (int r = 0; r < 4; r++) {
        const int row = rg * 4 + r;
        sc[row * 64 + e] = emb[r];
        d_CandE[(rbase + row) * 64 + e] = emb[r];
    }
    __syncthreads();

    // qrel: thread (a = e, rg) handles 4 rows: cand_emb @ Wq[:,a] + bk[a]
    {
        float acc[4];
        const float bk = sbk[e];
        #pragma unroll
        for (int r = 0; r < 4; r++) acc[r] = bk;
        for (int i = 0; i < 64; i++) {
            const float wv = Wq[i * 64 + e];
            #pragma unroll
            for (int r = 0; r < 4; r++)
                acc[r] = fmaf(sc[(rg * 4 + r) * 64 + i], wv, acc[r]);
        }
        const float wva = Wv[e];
        #pragma unroll
        for (int r = 0; r < 4; r++)
            d_Qv[(rbase + rg * 4 + r) * 64 + e] = make_float2(acc[r], wva);
    }
}

// ---------------------------------------------------------------------------
// din_mma: one CTA (256 threads = 8 warps) per batch row.
//   Warp = (mh = w&1 over m-tile pairs, nq = w>>1 over 16-row quarters).
//   Each B fragment pair feeds 2 MMAs (both m-tiles of the pair).
// ---------------------------------------------------------------------------
__global__ __launch_bounds__(256, 4) void din_mma(
    const float* __restrict__ hist,
    const int*   __restrict__ hlen)
{
    extern __shared__ uint32_t sH[];    // [<=200][64] bf16x2, swizzled
    __shared__ float  sPart[2 * 64];
    __shared__ float  sProb[256];
    __shared__ float2 sqv[64];
    __shared__ float  sRed[16];

    // pass-2 overlays on sH (post-score phase only)
    float* satt = (float*)sH;           // [8][128]
    float* savg = (float*)sH + 1024;

    const int b    = blockIdx.x;
    const int tid  = threadIdx.x;
    const int w    = tid >> 5;
    const int lane = tid & 31;
    const int len  = hlen[b];
    const int mh   = w & 1;             // m-tile pair {0,1} or {2,3}
    const int nq   = w >> 1;            // 16-row quarter of the chunk

    const float4* h4 = (const float4*)(hist + (long)b * 200 * 128);

    sProb[tid] = -1e9f;
    if (tid < 64) sqv[tid] = d_Qv[(long)b * 64 + tid];
    if (tid < 16) sRed[tid] = 0.f;

    // ---- stage only the rows that matter: ceil8(len) ----
    const int nrows = min(200, (len + 7) & ~7);
    for (int i = tid; i < nrows * 32; i += 256) {
        const int row = i >> 5, f4 = i & 31;
        const float4 x = h4[i];
        __nv_bfloat162 lo = __floats2bfloat162_rn(x.x, x.y);
        __nv_bfloat162 hi = __floats2bfloat162_rn(x.z, x.w);
        const int wds = (2 * f4) ^ ((row & 7) << 2);
        *(uint2*)(sH + row * 64 + wds) =
            make_uint2(*(uint32_t*)&lo, *(uint32_t*)&hi);
    }
    __syncthreads();

    const uint4* __restrict__ aB0 = (const uint4*)d_Afrag4 + ((mh * 2) << 8) + lane;
    const uint4* __restrict__ aB1 = aB0 + 256;
    const int rsub = lane >> 2;
    const int wq   = lane & 3;
    const int xo   = rsub << 2;

    // ---- full chunks of 64 rows (only those overlapping [0,len)) ----
    for (int c = 0; c < 3 && c * 64 < len; c++) {
        float acc[2][2][4];
        #pragma unroll
        for (int j = 0; j < 2; j++)
            #pragma unroll
            for (int nt = 0; nt < 2; nt++)
                #pragma unroll
                for (int q = 0; q < 4; q++) acc[j][nt][q] = 0.f;

        const int rbase = c * 64 + nq * 16 + rsub;
        #pragma unroll
        for (int k = 0; k < 8; k++) {
            const int w0 = (k * 8 + wq) ^ xo;
            const int w1 = (k * 8 + wq + 4) ^ xo;
            uint32_t bfr[2][2];
            #pragma unroll
            for (int nt = 0; nt < 2; nt++) {
                const uint32_t* bp = sH + (rbase + nt * 8) * 64;
                bfr[nt][0] = bp[w0];
                bfr[nt][1] = bp[w1];
            }
            {
                const uint4 av = aB0[k << 5];
                #pragma unroll
                for (int nt = 0; nt < 2; nt++)
                    mma_bf16(acc[0][nt], av.x, av.y, av.z, av.w,
                             bfr[nt][0], bfr[nt][1]);
            }
            {
                const uint4 av = aB1[k << 5];
                #pragma unroll
                for (int nt = 0; nt < 2; nt++)
                    mma_bf16(acc[1][nt], av.x, av.y, av.z, av.w,
                             bfr[nt][0], bfr[nt][1]);
            }
        }

        // epilogue: relu(q+D)*Wv over this warp's 32 a-values (2 m-tiles)
        const int abase = mh * 32 + rsub;
        const float2 qv00 = sqv[abase];
        const float2 qv01 = sqv[abase + 8];
        const float2 qv10 = sqv[abase + 16];
        const float2 qv11 = sqv[abase + 24];
        #pragma unroll
        for (int nt = 0; nt < 2; nt++) {
            float p0 = fmaxf(qv00.x + acc[0][nt][0], 0.f) * qv00.y
                     + fmaxf(qv01.x + acc[0][nt][2], 0.f) * qv01.y
                     + fmaxf(qv10.x + acc[1][nt][0], 0.f) * qv10.y
                     + fmaxf(qv11.x + acc[1][nt][2], 0.f) * qv11.y;
            float p1 = fmaxf(qv00.x + acc[0][nt][1], 0.f) * qv00.y
                     + fmaxf(qv01.x + acc[0][nt][3], 0.f) * qv01.y
                     + fmaxf(qv10.x + acc[1][nt][1], 0.f) * qv10.y
                     + fmaxf(qv11.x + acc[1][nt][3], 0.f) * qv11.y;
            #pragma unroll
            for (int off = 4; off < 32; off <<= 1) {
                p0 += __shfl_xor_sync(0xffffffffu, p0, off);
                p1 += __shfl_xor_sync(0xffffffffu, p1, off);
            }
            if (lane < 4) {
                const int s = nq * 16 + nt * 8 + lane * 2;
                sPart[mh * 64 + s]     = p0;
                sPart[mh * 64 + s + 1] = p1;
            }
        }
        __syncthreads();

        if (tid < 64) {
            const float sc = sPart[tid] + sPart[64 + tid];
            const int gr = c * 64 + tid;
            sProb[gr] = (gr < len) ? sc : -1e9f;
        }
        __syncthreads();
    }

    // ---- cleanup chunk rows 192-199 (only when len > 192) ----
    if (len > 192) {
        if (nq == 0) {
            float acc[2][4];
            #pragma unroll
            for (int j = 0; j < 2; j++)
                #pragma unroll
                for (int q = 0; q < 4; q++) acc[j][q] = 0.f;
            const uint32_t* bp = sH + (192 + rsub) * 64;
            #pragma unroll
            for (int k = 0; k < 8; k++) {
                const uint32_t b0 = bp[(k * 8 + wq) ^ xo];
                const uint32_t b1 = bp[(k * 8 + wq + 4) ^ xo];
                const uint4 av0 = aB0[k << 5];
                mma_bf16(acc[0], av0.x, av0.y, av0.z, av0.w, b0, b1);
                const uint4 av1 = aB1[k << 5];
                mma_bf16(acc[1], av1.x, av1.y, av1.z, av1.w, b0, b1);
            }
            const int abase = mh * 32 + rsub;
            const float2 qv00 = sqv[abase];
            const float2 qv01 = sqv[abase + 8];
            const float2 qv10 = sqv[abase + 16];
            const float2 qv11 = sqv[abase + 24];
            float p0 = fmaxf(qv00.x + acc[0][0], 0.f) * qv00.y
                     + fmaxf(qv01.x + acc[0][2], 0.f) * qv01.y
                     + fmaxf(qv10.x + acc[1][0], 0.f) * qv10.y
                     + fmaxf(qv11.x + acc[1][2], 0.f) * qv11.y;
            float p1 = fmaxf(qv00.x + acc[0][1], 0.f) * qv00.y
                     + fmaxf(qv01.x + acc[0][3], 0.f) * qv01.y
                     + fmaxf(qv10.x + acc[1][1], 0.f) * qv10.y
                     + fmaxf(qv11.x + acc[1][3], 0.f) * qv11.y;
            #pragma unroll
            for (int off = 4; off < 32; off <<= 1) {
                p0 += __shfl_xor_sync(0xffffffffu, p0, off);
                p1 += __shfl_xor_sync(0xffffffffu, p1, off);
            }
            if (lane < 4) {
                sPart[mh * 64 + lane * 2]     = p0;
                sPart[mh * 64 + lane * 2 + 1] = p1;
            }
        }
        __syncthreads();
        if (tid < 8) {
            const float sc = sPart[tid] + sPart[64 + tid];
            sProb[192 + tid] = (192 + tid < len) ? sc : -1e9f;
        }
        __syncthreads();
    }

    // ---- block softmax over 256 scores ----
    const float s = sProb[tid];
    float mx = s;
    #pragma unroll
    for (int off = 16; off; off >>= 1)
        mx = fmaxf(mx, __shfl_xor_sync(0xffffffffu, mx, off));
    if (lane == 0) sRed[w] = mx;
    __syncthreads();
    float M = sRed[0];
    #pragma unroll
    for (int i = 1; i < 8; i++) M = fmaxf(M, sRed[i]);
    const float p = __expf(s - M);
    float ps = p;
    #pragma unroll
    for (int off = 16; off; off >>= 1)
        ps += __shfl_xor_sync(0xffffffffu, ps, off);
    if (lane == 0) sRed[8 + w] = ps;
    __syncthreads();
    float T = 0.f;
    #pragma unroll
    for (int i = 0; i < 8; i++) T += sRed[8 + i];
    sProb[tid] = p;
    __syncthreads();

    // ---- pass 2: fp32 pooling (len-bounded, L2-hot re-read) ----
    unsigned long long pa0 = 0ull, pa1 = 0ull, av0 = 0ull, av1 = 0ull;
    const ulonglong2* h16 = (const ulonglong2*)h4;
    for (int r = w; r < len; r += 8) {
        const float pr = sProb[r];
        const ulonglong2 xx = h16[r * 32 + lane];
        const unsigned long long p2 = pack2(pr, pr);
        pa0 = ffma2(xx.x, p2, pa0);
        pa1 = ffma2(xx.y, p2, pa1);
        av0 = fadd2(av0, xx.x);
        av1 = fadd2(av1, xx.y);
    }
    __syncthreads();   // scores done -> sH region reusable
    *(ulonglong2*)(satt + w * 128 + lane * 4) = make_ulonglong2(pa0, pa1);
    *(ulonglong2*)(savg + w * 128 + lane * 4) = make_ulonglong2(av0, av1);
    __syncthreads();

    if (tid < 128) {
        float sa = 0.f, sv = 0.f;
        #pragma unroll
        for (int i = 0; i < 8; i++) {
            sa += satt[i * 128 + tid];
            sv += savg[i * 128 + tid];
        }
        d_Pool[(long)b * 256 + tid]       = sa / T;
        d_Pool[(long)b * 256 + 128 + tid] = sv / (float)len;
    }
}

// ---------------------------------------------------------------------------
// k2: batched E-projection + folded MLP + sigmoid. 8 rows per CTA, 1024 CTAs.
// ---------------------------------------------------------------------------
__global__ __launch_bounds__(256) void k2_kernel(
    const float* __restrict__ Wi, const float* __restrict__ bi,
    const float* __restrict__ Wo, const float* __restrict__ bo,
    float* __restrict__ out)
{
    __shared__ float sp[8 * 256];    // pool rows; later overlaid by xt/h2/h3
    __shared__ float sh1[8 * 128];

    const int tid = threadIdx.x;
    const int bid = blockIdx.x;
    const long rbase = (long)bid * 8;

    for (int i = tid; i < 8 * 64; i += 256)
        ((float4*)sp)[i] = ((const float4*)(d_Pool + rbase * 256))[i];
    __syncthreads();

    // E-projection: thread (e = tid&63, rg = tid>>6) handles 2 rows
    const int e  = tid & 63;
    const int rg = tid >> 6;
    float ai[2], aa[2];
    {
        const float be = bi[e];
        #pragma unroll
        for (int r = 0; r < 2; r++) { ai[r] = be; aa[r] = be; }
        for (int f = 0; f < 128; f++) {
            const float wv = Wi[f * 64 + e];
            #pragma unroll
            for (int r = 0; r < 2; r++) {
                const float* pr = sp + (rg * 2 + r) * 256;
                ai[r] = fmaf(pr[f],       wv, ai[r]);
                aa[r] = fmaf(pr[128 + f], wv, aa[r]);
            }
        }
    }
    __syncthreads();    // sp reads done; overlay xt [8][192]
    #pragma unroll
    for (int r = 0; r < 2; r++) {
        const int row = rg * 2 + r;
        sp[row * 192 + e]       = ai[r];
        sp[row * 192 + 128 + e] = aa[r];
        sp[row * 192 + 64 + e]  = d_CandE[(rbase + row) * 64 + e];
    }
    __syncthreads();

    // layer 1: thread (h = tid&127, rg2 = tid>>7) handles 4 rows
    {
        const int h = tid & 127, rg2 = tid >> 7;
        float acc[4];
        const float bb = d_b1f[h];
        #pragma unroll
        for (int r = 0; r < 4; r++) acc[r] = bb;
        for (int i = 0; i < 192; i++) {
            const float wv = d_W1f[i * 128 + h];
            #pragma unroll
            for (int r = 0; r < 4; r++)
                acc[r] = fmaf(sp[(rg2 * 4 + r) * 192 + i], wv, acc[r]);
        }
        #pragma unroll
        for (int r = 0; r < 4; r++)
            sh1[(rg2 * 4 + r) * 128 + h] = fmaxf(acc[r], 0.f);
    }
    __syncthreads();

    // layer 2 -> h2 at sp[0..511]
    {
        float acc[2];
        const float bb = d_b2f[e];
        acc[0] = bb; acc[1] = bb;
        for (int i = 0; i < 128; i++) {
            const float wv = d_W2f[i * 64 + e];
            #pragma unroll
            for (int r = 0; r < 2; r++)
                acc[r] = fmaf(sh1[(rg * 2 + r) * 128 + i], wv, acc[r]);
        }
        #pragma unroll
        for (int r = 0; r < 2; r++)
            sp[(rg * 2 + r) * 64 + e] = fmaxf(acc[r], 0.f);
    }
    __syncthreads();

    // layer 3 -> h3 at sp[512..767]
    {
        const int o = tid & 31, rg3 = tid >> 5;
        float acc = d_b3f[o];
        for (int i = 0; i < 64; i++)
            acc = fmaf(sp[rg3 * 64 + i], d_W3f[i * 32 + o], acc);
        sp[512 + rg3 * 32 + o] = fmaxf(acc, 0.f);
    }
    __syncthreads();

    // output: sigmoid(h3 @ Wo + bo)
    if (tid < 8) {
        float z = bo[0];
        #pragma unroll
        for (int j = 0; j < 32; j++)
            z = fmaf(sp[512 + tid * 32 + j], Wo[j], z);
        out[rbase + tid] = 1.f / (1.f + __expf(-z));
    }
}

// ---------------------------------------------------------------------------
extern "C" void kernel_launch(void* const* d_in, const int* in_sizes, int n_in,
                              void* d_out, int out_size)
{
    const float* cand = (const float*)d_in[0];
    const float* hist = (const float*)d_in[1];
    const int*   hlen = (const int*)d_in[2];
    const float* Wi   = (const float*)d_in[3];
    const float* bi   = (const float*)d_in[4];
    const float* Wq   = (const float*)d_in[5];
    const float* Wk   = (const float*)d_in[6];
    const float* Wv   = (const float*)d_in[7];
    const float* W1   = (const float*)d_in[8];
    const float* b1   = (const float*)d_in[9];
    const float* g1   = (const float*)d_in[10];
    const float* be1  = (const float*)d_in[11];
    const float* m1   = (const float*)d_in[12];
    const float* v1   = (const float*)d_in[13];
    const float* W2   = (const float*)d_in[14];
    const float* b2   = (const float*)d_in[15];
    const float* g2   = (const float*)d_in[16];
    const float* be2  = (const float*)d_in[17];
    const float* m2   = (const float*)d_in[18];
    const float* v2   = (const float*)d_in[19];
    const float* W3   = (const float*)d_in[20];
    const float* b3   = (const float*)d_in[21];
    const float* g3   = (const float*)d_in[22];
    const float* be3  = (const float*)d_in[23];
    const float* m3   = (const float*)d_in[24];
    const float* v3   = (const float*)d_in[25];
    const float* Wo   = (const float*)d_in[26];
    const float* bo   = (const float*)d_in[27];
    float* out = (float*)d_out;

    const int dyn_smem = 200 * 64 * 4;   // 51200 B history tile
    cudaFuncSetAttribute(din_mma, cudaFuncAttributeMaxDynamicSharedMemorySize,
                         dyn_smem);

    k0_kernel<<<512, 256>>>(cand, Wi, bi, Wq, Wk, Wv,
                            W1, b1, g1, be1, m1, v1,
                            W2, b2, g2, be2, m2, v2,
                            W3, b3, g3, be3, m3, v3);
    din_mma<<<8192, 256, dyn_smem>>>(hist, hlen);
    k2_kernel<<<1024, 256>>>(Wi, bi, Wo, bo, out);
}

// round 12
// speedup vs baseline: 1.0499x; 1.0499x over previous
#include <cuda_runtime.h>
#include <cuda_bf16.h>
#include <cstdint>

// ---------------------------------------------------------------------------
// DIN forward, round 12: best-known combination.
//   k0 (1024 CTAs x 8 rows): weight folding (grid-stride) + batched cand
//       projections (qrel/Wv table, cand embedding table).
//   din_mma (8192 CTAs): round-9 proven config — stage ceil8(len) rows ->
//       bf16 m16n8k16 score GEMM, 4mt x 2nh warp tiling -> softmax ->
//       len-bounded fp32 pooling -> pooled vectors.
//   k2 (1024 CTAs x 8 rows): E-projection + BN-folded MLP + sigmoid.
// ---------------------------------------------------------------------------

#define EPSBN 1e-5f

// ---- device scratch ----
__device__ uint4  d_Afrag4[4 * 8 * 32];   // [mt][k][lane] bf16x2 A-fragments
__device__ float  d_W1f[192 * 128];       // BN-folded MLP weights [in][out]
__device__ float  d_b1f[128];
__device__ float  d_W2f[128 * 64];
__device__ float  d_b2f[64];
__device__ float  d_W3f[64 * 32];
__device__ float  d_b3f[32];
__device__ float2 d_Qv[8192 * 64];        // (qrel, Wv) per (b, a)
__device__ float  d_CandE[8192 * 64];     // cand embedding (with bi)
__device__ float  d_Pool[8192 * 256];     // [spa(128) | spv(128)] per b

// ---- packed f32x2 helpers ----
__device__ __forceinline__ unsigned long long ffma2(unsigned long long a,
                                                    unsigned long long b,
                                                    unsigned long long c) {
    unsigned long long d;
    asm("fma.rn.f32x2 %0, %1, %2, %3;" : "=l"(d) : "l"(a), "l"(b), "l"(c));
    return d;
}
__device__ __forceinline__ unsigned long long fadd2(unsigned long long a,
                                                    unsigned long long b) {
    unsigned long long d;
    asm("add.rn.f32x2 %0, %1, %2;" : "=l"(d) : "l"(a), "l"(b));
    return d;
}
__device__ __forceinline__ unsigned long long pack2(float lo, float hi) {
    unsigned long long r;
    asm("mov.b64 %0, {%1, %2};" : "=l"(r) : "f"(lo), "f"(hi));
    return r;
}

// bf16 mma: D += A*B (A row-major m16k16, B col-major k16n8, fp32 acc)
__device__ __forceinline__ void mma_bf16(float c[4], uint32_t a0, uint32_t a1,
                                         uint32_t a2, uint32_t a3,
                                         uint32_t b0, uint32_t b1) {
    asm volatile(
        "mma.sync.aligned.m16n8k16.row.col.f32.bf16.bf16.f32 "
        "{%0,%1,%2,%3}, {%4,%5,%6,%7}, {%8,%9}, {%0,%1,%2,%3};"
        : "+f"(c[0]), "+f"(c[1]), "+f"(c[2]), "+f"(c[3])
        : "r"(a0), "r"(a1), "r"(a2), "r"(a3), "r"(b0), "r"(b1));
}

// ---------------------------------------------------------------------------
// k0: weight folds (grid-stride) + per-CTA batched cand projections.
// 1024 CTAs x 256 threads; 8 batch rows per CTA.
// ---------------------------------------------------------------------------
__global__ __launch_bounds__(256) void k0_kernel(
    const float* __restrict__ cand,
    const float* __restrict__ Wi, const float* __restrict__ bi,
    const float* __restrict__ Wq, const float* __restrict__ Wk,
    const float* __restrict__ Wv,
    const float* __restrict__ W1, const float* __restrict__ b1,
    const float* __restrict__ g1, const float* __restrict__ be1,
    const float* __restrict__ m1, const float* __restrict__ v1,
    const float* __restrict__ W2, const float* __restrict__ b2,
    const float* __restrict__ g2, const float* __restrict__ be2,
    const float* __restrict__ m2, const float* __restrict__ v2,
    const float* __restrict__ W3, const float* __restrict__ b3,
    const float* __restrict__ g3, const float* __restrict__ be3,
    const float* __restrict__ m3, const float* __restrict__ v3)
{
    __shared__ float sc[8 * 128];    // cand rows; later overlaid by cand_emb
    __shared__ float sbk[64];

    const int tid = threadIdx.x;
    const int bid = blockIdx.x;
    const int t0 = bid * 256 + tid;
    const int stride = gridDim.x * 256;

    // ---- grid-stride weight folding ----
    for (int idx = t0; idx < 1024; idx += stride) {
        const int lane = idx & 31;
        const int k8   = (idx >> 5) & 7;
        const int mt   = idx >> 8;
        uint32_t comp[4];
        #pragma unroll
        for (int j = 0; j < 4; j++) {
            const int a  = mt * 16 + (lane >> 2) + ((j & 1) << 3);
            const int f0 = k8 * 16 + 2 * (lane & 3) + ((j >> 1) << 3);
            float s0 = 0.f, s1 = 0.f;
            for (int e = 0; e < 64; e++) {
                const float wka = Wk[e * 64 + a];
                s0 = fmaf(Wi[f0 * 64 + e],       wka, s0);
                s1 = fmaf(Wi[(f0 + 1) * 64 + e], wka, s1);
            }
            __nv_bfloat162 pr = __floats2bfloat162_rn(s0, s1);
            comp[j] = *(uint32_t*)&pr;
        }
        d_Afrag4[idx] = make_uint4(comp[0], comp[1], comp[2], comp[3]);
    }
    for (int idx = t0; idx < 192 * 128; idx += stride) {
        const int h = idx & 127;
        d_W1f[idx] = W1[idx] * (g1[h] * rsqrtf(v1[h] + EPSBN));
    }
    for (int h = t0; h < 128; h += stride) {
        const float scl = g1[h] * rsqrtf(v1[h] + EPSBN);
        d_b1f[h] = (b1[h] - m1[h]) * scl + be1[h];
    }
    for (int idx = t0; idx < 128 * 64; idx += stride) {
        const int h = idx & 63;
        d_W2f[idx] = W2[idx] * (g2[h] * rsqrtf(v2[h] + EPSBN));
    }
    for (int h = t0; h < 64; h += stride) {
        const float scl = g2[h] * rsqrtf(v2[h] + EPSBN);
        d_b2f[h] = (b2[h] - m2[h]) * scl + be2[h];
    }
    for (int idx = t0; idx < 64 * 32; idx += stride) {
        const int h = idx & 31;
        d_W3f[idx] = W3[idx] * (g3[h] * rsqrtf(v3[h] + EPSBN));
    }
    for (int h = t0; h < 32; h += stride) {
        const float scl = g3[h] * rsqrtf(v3[h] + EPSBN);
        d_b3f[h] = (b3[h] - m3[h]) * scl + be3[h];
    }

    // ---- per-CTA: 8 candidate rows ----
    const long rbase = (long)bid * 8;
    for (int i = tid; i < 8 * 32; i += 256)
        ((float4*)sc)[i] = ((const float4*)(cand + rbase * 128))[i];
    if (tid < 64) {   // bk[a] = bi @ Wk[:,a]
        float s = 0.f;
        for (int e = 0; e < 64; e++)
            s = fmaf(bi[e], Wk[e * 64 + tid], s);
        sbk[tid] = s;
    }
    __syncthreads();

    // cand_emb: thread (e = tid&63, rg = tid>>6) handles 2 rows
    const int e  = tid & 63;
    const int rg = tid >> 6;
    float emb[2];
    {
        emb[0] = bi[e]; emb[1] = bi[e];
        for (int f = 0; f < 128; f++) {
            const float wv = Wi[f * 64 + e];
            emb[0] = fmaf(sc[(rg * 2) * 128 + f],     wv, emb[0]);
            emb[1] = fmaf(sc[(rg * 2 + 1) * 128 + f], wv, emb[1]);
        }
    }
    __syncthreads();    // sc reads done; overlay emb
    #pragma unroll
    for (int r = 0; r < 2; r++) {
        const int row = rg * 2 + r;
        sc[row * 64 + e] = emb[r];
        d_CandE[(rbase + row) * 64 + e] = emb[r];
    }
    __syncthreads();

    // qrel: thread (a = e, rg) handles 2 rows: cand_emb @ Wq[:,a] + bk[a]
    {
        float acc[2];
        const float bk = sbk[e];
        acc[0] = bk; acc[1] = bk;
        for (int i = 0; i < 64; i++) {
            const float wv = Wq[i * 64 + e];
            acc[0] = fmaf(sc[(rg * 2) * 64 + i],     wv, acc[0]);
            acc[1] = fmaf(sc[(rg * 2 + 1) * 64 + i], wv, acc[1]);
        }
        const float wva = Wv[e];
        #pragma unroll
        for (int r = 0; r < 2; r++)
            d_Qv[(rbase + rg * 2 + r) * 64 + e] = make_float2(acc[r], wva);
    }
}

// ---------------------------------------------------------------------------
// din_mma: one CTA (256 threads = 8 warps) per batch row. Round-9 proven
// config: warp = (mt = w&3 over the a-dim, nh = w>>2 over 32-row halves).
// ---------------------------------------------------------------------------
__global__ __launch_bounds__(256, 4) void din_mma(
    const float* __restrict__ hist,
    const int*   __restrict__ hlen)
{
    extern __shared__ uint32_t sH[];    // [<=200][64] bf16x2, swizzled
    __shared__ float  sPart[4 * 64];
    __shared__ float  sProb[256];
    __shared__ float2 sqv[64];
    __shared__ float  sRed[16];

    // pass-2 overlays on sH (post-score phase only)
    float* satt = (float*)sH;           // [8][128]
    float* savg = (float*)sH + 1024;

    const int b    = blockIdx.x;
    const int tid  = threadIdx.x;
    const int w    = tid >> 5;
    const int lane = tid & 31;
    const int len  = hlen[b];
    const int mt   = w & 3;
    const int nh   = w >> 2;

    const float4* h4 = (const float4*)(hist + (long)b * 200 * 128);

    sProb[tid] = -1e9f;
    if (tid < 64) sqv[tid] = d_Qv[(long)b * 64 + tid];

    // ---- stage only the rows that matter: ceil8(len) ----
    const int nrows = min(200, (len + 7) & ~7);
    for (int i = tid; i < nrows * 32; i += 256) {
        const int row = i >> 5, f4 = i & 31;
        const float4 x = h4[i];
        __nv_bfloat162 lo = __floats2bfloat162_rn(x.x, x.y);
        __nv_bfloat162 hi = __floats2bfloat162_rn(x.z, x.w);
        const int wds = (2 * f4) ^ ((row & 7) << 2);
        *(uint2*)(sH + row * 64 + wds) =
            make_uint2(*(uint32_t*)&lo, *(uint32_t*)&hi);
    }
    __syncthreads();

    const uint4* __restrict__ aB4 = (const uint4*)d_Afrag4 + (mt << 8) + lane;
    const int rsub = lane >> 2;
    const int wq   = lane & 3;
    const int xo   = rsub << 2;

    // ---- full chunks of 64 rows (only those overlapping [0,len)) ----
    for (int c = 0; c < 3 && c * 64 < len; c++) {
        float acc[4][4];
        #pragma unroll
        for (int nt = 0; nt < 4; nt++)
            #pragma unroll
            for (int j = 0; j < 4; j++) acc[nt][j] = 0.f;

        const int rbase = c * 64 + nh * 32 + rsub;
        #pragma unroll
        for (int k = 0; k < 8; k++) {
            const uint4 av = aB4[k << 5];
            const int w0 = (k * 8 + wq) ^ xo;
            const int w1 = (k * 8 + wq + 4) ^ xo;
            #pragma unroll
            for (int nt = 0; nt < 4; nt++) {
                const uint32_t* bp = sH + (rbase + nt * 8) * 64;
                mma_bf16(acc[nt], av.x, av.y, av.z, av.w, bp[w0], bp[w1]);
            }
        }

        const int a0i = mt * 16 + rsub;
        const float2 qv0 = sqv[a0i];
        const float2 qv1 = sqv[a0i + 8];
        #pragma unroll
        for (int nt = 0; nt < 4; nt++) {
            float p0 = fmaxf(qv0.x + acc[nt][0], 0.f) * qv0.y
                     + fmaxf(qv1.x + acc[nt][2], 0.f) * qv1.y;
            float p1 = fmaxf(qv0.x + acc[nt][1], 0.f) * qv0.y
                     + fmaxf(qv1.x + acc[nt][3], 0.f) * qv1.y;
            #pragma unroll
            for (int off = 4; off < 32; off <<= 1) {
                p0 += __shfl_xor_sync(0xffffffffu, p0, off);
                p1 += __shfl_xor_sync(0xffffffffu, p1, off);
            }
            if (lane < 4) {
                const int s = nh * 32 + nt * 8 + lane * 2;
                sPart[mt * 64 + s]     = p0;
                sPart[mt * 64 + s + 1] = p1;
            }
        }
        __syncthreads();

        if (tid < 64) {
            const float sc = sPart[tid] + sPart[64 + tid]
                           + sPart[128 + tid] + sPart[192 + tid];
            const int gr = c * 64 + tid;
            sProb[gr] = (gr < len) ? sc : -1e9f;
        }
        __syncthreads();
    }

    // ---- cleanup chunk rows 192-199 (only when len > 192) ----
    if (len > 192) {
        if (nh == 0) {
            float acc[4];
            #pragma unroll
            for (int j = 0; j < 4; j++) acc[j] = 0.f;
            const uint32_t* bp = sH + (192 + rsub) * 64;
            #pragma unroll
            for (int k = 0; k < 8; k++) {
                const uint4 av = aB4[k << 5];
                mma_bf16(acc, av.x, av.y, av.z, av.w,
                         bp[(k * 8 + wq) ^ xo], bp[(k * 8 + wq + 4) ^ xo]);
            }
            const int a0i = mt * 16 + rsub;
            const float2 qv0 = sqv[a0i];
            const float2 qv1 = sqv[a0i + 8];
            float p0 = fmaxf(qv0.x + acc[0], 0.f) * qv0.y
                     + fmaxf(qv1.x + acc[2], 0.f) * qv1.y;
            float p1 = fmaxf(qv0.x + acc[1], 0.f) * qv0.y
                     + fmaxf(qv1.x + acc[3], 0.f) * qv1.y;
            #pragma unroll
            for (int off = 4; off < 32; off <<= 1) {
                p0 += __shfl_xor_sync(0xffffffffu, p0, off);
                p1 += __shfl_xor_sync(0xffffffffu, p1, off);
            }
            if (lane < 4) {
                sPart[mt * 64 + lane * 2]     = p0;
                sPart[mt * 64 + lane * 2 + 1] = p1;
            }
        }
        __syncthreads();
        if (tid < 8) {
            const float sc = sPart[tid] + sPart[64 + tid]
                           + sPart[128 + tid] + sPart[192 + tid];
            sProb[192 + tid] = (192 + tid < len) ? sc : -1e9f;
        }
        __syncthreads();
    }

    // ---- block softmax over 256 scores ----
    const float s = sProb[tid];
    float mx = s;
    #pragma unroll
    for (int off = 16; off; off >>= 1)
        mx = fmaxf(mx, __shfl_xor_sync(0xffffffffu, mx, off));
    if (lane == 0) sRed[w] = mx;
    __syncthreads();
    float M = sRed[0];
    #pragma unroll
    for (int i = 1; i < 8; i++) M = fmaxf(M, sRed[i]);
    const float p = __expf(s - M);
    float ps = p;
    #pragma unroll
    for (int off = 16; off; off >>= 1)
        ps += __shfl_xor_sync(0xffffffffu, ps, off);
    if (lane == 0) sRed[8 + w] = ps;
    __syncthreads();
    float T = 0.f;
    #pragma unroll
    for (int i = 0; i < 8; i++) T += sRed[8 + i];
    sProb[tid] = p;
    __syncthreads();

    // ---- pass 2: fp32 pooling (len-bounded, L2-hot re-read) ----
    unsigned long long pa0 = 0ull, pa1 = 0ull, av0 = 0ull, av1 = 0ull;
    const ulonglong2* h16 = (const ulonglong2*)h4;
    for (int r = w; r < len; r += 8) {
        const float pr = sProb[r];
        const ulonglong2 xx = h16[r * 32 + lane];
        const unsigned long long p2 = pack2(pr, pr);
        pa0 = ffma2(xx.x, p2, pa0);
        pa1 = ffma2(xx.y, p2, pa1);
        av0 = fadd2(av0, xx.x);
        av1 = fadd2(av1, xx.y);
    }
    __syncthreads();   // scores done -> sH region reusable
    *(ulonglong2*)(satt + w * 128 + lane * 4) = make_ulonglong2(pa0, pa1);
    *(ulonglong2*)(savg + w * 128 + lane * 4) = make_ulonglong2(av0, av1);
    __syncthreads();

    if (tid < 128) {
        float sa = 0.f, sv = 0.f;
        #pragma unroll
        for (int i = 0; i < 8; i++) {
            sa += satt[i * 128 + tid];
            sv += savg[i * 128 + tid];
        }
        d_Pool[(long)b * 256 + tid]       = sa / T;
        d_Pool[(long)b * 256 + 128 + tid] = sv / (float)len;
    }
}

// ---------------------------------------------------------------------------
// k2: batched E-projection + folded MLP + sigmoid. 8 rows per CTA, 1024 CTAs.
// ---------------------------------------------------------------------------
__global__ __launch_bounds__(256) void k2_kernel(
    const float* __restrict__ Wi, const float* __restrict__ bi,
    const float* __restrict__ Wo, const float* __restrict__ bo,
    float* __restrict__ out)
{
    __shared__ float sp[8 * 256];    // pool rows; later overlaid by xt/h2/h3
    __shared__ float sh1[8 * 128];

    const int tid = threadIdx.x;
    const int bid = blockIdx.x;
    const long rbase = (long)bid * 8;

    for (int i = tid; i < 8 * 64; i += 256)
        ((float4*)sp)[i] = ((const float4*)(d_Pool + rbase * 256))[i];
    __syncthreads();

    // E-projection: thread (e = tid&63, rg = tid>>6) handles 2 rows
    const int e  = tid & 63;
    const int rg = tid >> 6;
    float ai[2], aa[2];
    {
        const float be = bi[e];
        #pragma unroll
        for (int r = 0; r < 2; r++) { ai[r] = be; aa[r] = be; }
        for (int f = 0; f < 128; f++) {
            const float wv = Wi[f * 64 + e];
            #pragma unroll
            for (int r = 0; r < 2; r++) {
                const float* pr = sp + (rg * 2 + r) * 256;
                ai[r] = fmaf(pr[f],       wv, ai[r]);
                aa[r] = fmaf(pr[128 + f], wv, aa[r]);
            }
        }
    }
    __syncthreads();    // sp reads done; overlay xt [8][192]
    #pragma unroll
    for (int r = 0; r < 2; r++) {
        const int row = rg * 2 + r;
        sp[row * 192 + e]       = ai[r];
        sp[row * 192 + 128 + e] = aa[r];
        sp[row * 192 + 64 + e]  = d_CandE[(rbase + row) * 64 + e];
    }
    __syncthreads();

    // layer 1: thread (h = tid&127, rg2 = tid>>7) handles 4 rows
    {
        const int h = tid & 127, rg2 = tid >> 7;
        float acc[4];
        const float bb = d_b1f[h];
        #pragma unroll
        for (int r = 0; r < 4; r++) acc[r] = bb;
        for (int i = 0; i < 192; i++) {
            const float wv = d_W1f[i * 128 + h];
            #pragma unroll
            for (int r = 0; r < 4; r++)
                acc[r] = fmaf(sp[(rg2 * 4 + r) * 192 + i], wv, acc[r]);
        }
        #pragma unroll
        for (int r = 0; r < 4; r++)
            sh1[(rg2 * 4 + r) * 128 + h] = fmaxf(acc[r], 0.f);
    }
    __syncthreads();

    // layer 2 -> h2 at sp[0..511]
    {
        float acc[2];
        const float bb = d_b2f[e];
        acc[0] = bb; acc[1] = bb;
        for (int i = 0; i < 128; i++) {
            const float wv = d_W2f[i * 64 + e];
            #pragma unroll
            for (int r = 0; r < 2; r++)
                acc[r] = fmaf(sh1[(rg * 2 + r) * 128 + i], wv, acc[r]);
        }
        #pragma unroll
        for (int r = 0; r < 2; r++)
            sp[(rg * 2 + r) * 64 + e] = fmaxf(acc[r], 0.f);
    }
    __syncthreads();

    // layer 3 -> h3 at sp[512..767]
    {
        const int o = tid & 31, rg3 = tid >> 5;
        float acc = d_b3f[o];
        for (int i = 0; i < 64; i++)
            acc = fmaf(sp[rg3 * 64 + i], d_W3f[i * 32 + o], acc);
        sp[512 + rg3 * 32 + o] = fmaxf(acc, 0.f);
    }
    __syncthreads();

    // output: sigmoid(h3 @ Wo + bo)
    if (tid < 8) {
        float z = bo[0];
        #pragma unroll
        for (int j = 0; j < 32; j++)
            z = fmaf(sp[512 + tid * 32 + j], Wo[j], z);
        out[rbase + tid] = 1.f / (1.f + __expf(-z));
    }
}

// ---------------------------------------------------------------------------
extern "C" void kernel_launch(void* const* d_in, const int* in_sizes, int n_in,
                              void* d_out, int out_size)
{
    const float* cand = (const float*)d_in[0];
    const float* hist = (const float*)d_in[1];
    const int*   hlen = (const int*)d_in[2];
    const float* Wi   = (const float*)d_in[3];
    const float* bi   = (const float*)d_in[4];
    const float* Wq   = (const float*)d_in[5];
    const float* Wk   = (const float*)d_in[6];
    const float* Wv   = (const float*)d_in[7];
    const float* W1   = (const float*)d_in[8];
    const float* b1   = (const float*)d_in[9];
    const float* g1   = (const float*)d_in[10];
    const float* be1  = (const float*)d_in[11];
    const float* m1   = (const float*)d_in[12];
    const float* v1   = (const float*)d_in[13];
    const float* W2   = (const float*)d_in[14];
    const float* b2   = (const float*)d_in[15];
    const float* g2   = (const float*)d_in[16];
    const float* be2  = (const float*)d_in[17];
    const float* m2   = (const float*)d_in[18];
    const float* v2   = (const float*)d_in[19];
    const float* W3   = (const float*)d_in[20];
    const float* b3   = (const float*)d_in[21];
    const float* g3   = (const float*)d_in[22];
    const float* be3  = (const float*)d_in[23];
    const float* m3   = (const float*)d_in[24];
    const float* v3   = (const float*)d_in[25];
    const float* Wo   = (const float*)d_in[26];
    const float* bo   = (const float*)d_in[27];
    float* out = (float*)d_out;

    const int dyn_smem = 200 * 64 * 4;   // 51200 B history tile
    cudaFuncSetAttribute(din_mma, cudaFuncAttributeMaxDynamicSharedMemorySize,
                         dyn_smem);

    k0_kernel<<<1024, 256>>>(cand, Wi, bi, Wq, Wk, Wv,
                             W1, b1, g1, be1, m1, v1,
                             W2, b2, g2, be2, m2, v2,
                             W3, b3, g3, be3, m3, v3);
    din_mma<<<8192, 256, dyn_smem>>>(hist, hlen);
    k2_kernel<<<1024, 256>>>(Wi, bi, Wo, bo, out);
}